// round 11
// baseline (speedup 1.0000x reference)
#include <cuda_runtime.h>

// Problem geometry (fixed by the dataset)
#define D_IN 384
#define H_IN 128
#define W_IN 128
#define NVOX (D_IN * H_IN * W_IN)        // 6,291,456 input voxels
#define S0 128
#define S1 128
#define S2 128
#define NOUT (S0 * S1 * S2)              // 2,097,152 per channel
// flow scale = (x.shape[d]-1)/(flow.shape[d]-1) = 1.0 for all dims here.

// Channel-interleaved scratch accumulators: [z][y][x][c], c=2 (8 bytes/voxel).
// A receives even-xi corner pairs (16B-aligned at 2*flat).
// B receives odd-xi corner pairs; effective base g_B+2 floats (8B offset), so
// odd-flat pair addresses are 16B-aligned there.
//
// ZERO INVARIANT: zero-initialized at module load (CUDA guarantees zero-init
// of __device__ globals). finalize_kernel restores every byte it reads back
// to zero, so every kernel_launch call — first and replayed — begins with
// zeroed scratch. No separate zeroing kernel is needed.
__device__ __align__(16) float g_A[2 * NOUT];
__device__ __align__(16) float g_B[2 * NOUT + 8];

__device__ __forceinline__ void red_add_v2(float* p, float a, float b) {
    asm volatile("red.global.add.v2.f32 [%0], {%1, %2};"
                 :: "l"(p), "f"(a), "f"(b) : "memory");
}
__device__ __forceinline__ void red_add_v4(float* p, float a, float b, float c, float d) {
    asm volatile("red.global.add.v4.f32 [%0], {%1, %2, %3, %4};"
                 :: "l"(p), "f"(a), "f"(b), "f"(c), "f"(d) : "memory");
}

// Splat the trilinear footprint of one voxel. All weights/indices already
// replicate-clipped and z/y-merged by the caller.
__device__ __forceinline__ void splat_one(
    float v0, float m, float cz, float cy, float cx)
{
    // z corners (merged when both clip to the same plane).
    int z0, z1; float wz0, wz1; bool two_z;
    {
        float f0 = floorf(cz); float t = cz - f0;
        int i0 = (int)f0;
        z0 = min(max(i0, 0), S0 - 1);
        z1 = min(max(i0 + 1, 0), S0 - 1);
        two_z = (z0 != z1);
        wz0 = two_z ? (1.f - t) : 1.f;
        wz1 = t;
    }
    int y0, y1; float wy0, wy1; bool two_y;
    {
        float f0 = floorf(cy); float t = cy - f0;
        int i0 = (int)f0;
        y0 = min(max(i0, 0), S1 - 1);
        y1 = min(max(i0 + 1, 0), S1 - 1);
        two_y = (y0 != y1);
        wy0 = two_y ? (1.f - t) : 1.f;
        wy1 = t;
    }
    int xi0; float wx0, wx1; bool two_x;
    {
        float f0 = floorf(cx); float t = cx - f0;
        int i0 = (int)f0;
        int c0 = min(max(i0, 0), S2 - 1);
        int c1 = min(max(i0 + 1, 0), S2 - 1);
        two_x = (c0 != c1);
        xi0 = c0;
        wx0 = two_x ? (1.f - t) : 1.f;
        wx1 = t;
    }

    // Pair buffer: even xi0 -> A, odd xi0 -> B (offset base => 16B aligned).
    float* pair_buf = (xi0 & 1) ? (g_B + 2) : g_A;

    int base0 = (z0 * S1 + y0) * S2 + xi0;     // (z0, y0)
    if (two_x) {
        float w00 = wz0 * wy0;
        red_add_v4(pair_buf + 2 * base0,
                   v0 * (w00 * wx0), m * (w00 * wx0),
                   v0 * (w00 * wx1), m * (w00 * wx1));
        if (two_y) {
            int b01 = (z0 * S1 + y1) * S2 + xi0;
            float w01 = wz0 * wy1;
            red_add_v4(pair_buf + 2 * b01,
                       v0 * (w01 * wx0), m * (w01 * wx0),
                       v0 * (w01 * wx1), m * (w01 * wx1));
        }
        if (two_z) {
            int b10 = (z1 * S1 + y0) * S2 + xi0;
            float w10 = wz1 * wy0;
            red_add_v4(pair_buf + 2 * b10,
                       v0 * (w10 * wx0), m * (w10 * wx0),
                       v0 * (w10 * wx1), m * (w10 * wx1));
            if (two_y) {
                int b11 = (z1 * S1 + y1) * S2 + xi0;
                float w11 = wz1 * wy1;
                red_add_v4(pair_buf + 2 * b11,
                           v0 * (w11 * wx0), m * (w11 * wx0),
                           v0 * (w11 * wx1), m * (w11 * wx1));
            }
        }
    } else {
        float w00 = wz0 * wy0;
        red_add_v2(g_A + 2 * base0, v0 * w00, m * w00);
        if (two_y) {
            int b01 = (z0 * S1 + y1) * S2 + xi0;
            float w01 = wz0 * wy1;
            red_add_v2(g_A + 2 * b01, v0 * w01, m * w01);
        }
        if (two_z) {
            int b10 = (z1 * S1 + y0) * S2 + xi0;
            float w10 = wz1 * wy0;
            red_add_v2(g_A + 2 * b10, v0 * w10, m * w10);
            if (two_y) {
                int b11 = (z1 * S1 + y1) * S2 + xi0;
                float w11 = wz1 * wy1;
                red_add_v2(g_A + 2 * b11, v0 * w11, m * w11);
            }
        }
    }
}

// 4 consecutive-ix voxels per thread: 5 float4 streaming loads, 4 independent
// splat chains for ILP/MLP.
__global__ __launch_bounds__(256, 4) void splat_kernel(
    const float4* __restrict__ x4,
    const float4* __restrict__ flow4,
    const float4* __restrict__ mask4)
{
    int tid = blockIdx.x * blockDim.x + threadIdx.x;   // handles voxels 4t..4t+3
    int vbase = tid * 4;

    int ix = vbase & (W_IN - 1);                       // 0,4,...,124
    int iy = (vbase >> 7) & (H_IN - 1);
    int iz = vbase >> 14;

    // 5 vector streaming loads (evict-first: read-once input must not evict
    // the RED-hot scratch from L2).
    const int NV4 = NVOX / 4;
    float4 mv = __ldcs(mask4 + tid);
    float4 xv = __ldcs(x4 + tid);
    float4 fz = __ldcs(flow4 + tid);
    float4 fy = __ldcs(flow4 + tid + NV4);
    float4 fx = __ldcs(flow4 + tid + 2 * NV4);

    float mm[4] = {mv.x, mv.y, mv.z, mv.w};
    float xx[4] = {xv.x, xv.y, xv.z, xv.w};
    float zz[4] = {fz.x, fz.y, fz.z, fz.w};
    float yy[4] = {fy.x, fy.y, fy.z, fy.w};
    float ff[4] = {fx.x, fx.y, fx.z, fx.w};

    float fiz = (float)iz, fiy = (float)iy;
    #pragma unroll
    for (int j = 0; j < 4; j++) {
        splat_one(xx[j] * mm[j], mm[j],
                  zz[j] + fiz,
                  yy[j] + fiy,
                  ff[j] + (float)(ix + j));
    }
}

// out[c][i] = A[i][c] + B[i][c]; 8 voxels per thread, float4 traffic on A/out.
// Also restores the zero invariant: every scratch address this thread reads
// is written back to zero (same-thread RAW only — B is re-zeroed with the
// exact same 8B-aligned float2 granules it loads, so no cross-thread overlap).
__global__ __launch_bounds__(256) void finalize_kernel(float* __restrict__ out) {
    int i = blockIdx.x * blockDim.x + threadIdx.x;   // 8 output voxels each
    float4* A4 = (float4*)g_A;                       // 2 voxels per entry
    float2* Bv = (float2*)(g_B + 2);                 // 1 voxel per entry

    float4 a[4];
    float2 b[8];
    #pragma unroll
    for (int k = 0; k < 4; k++) a[k] = A4[4 * i + k];
    #pragma unroll
    for (int k = 0; k < 8; k++) b[k] = Bv[8 * i + k];

    float4 o0a = make_float4(a[0].x + b[0].x, a[0].z + b[1].x,
                             a[1].x + b[2].x, a[1].z + b[3].x);
    float4 o0b = make_float4(a[2].x + b[4].x, a[2].z + b[5].x,
                             a[3].x + b[6].x, a[3].z + b[7].x);
    float4 o1a = make_float4(a[0].y + b[0].y, a[0].w + b[1].y,
                             a[1].y + b[2].y, a[1].w + b[3].y);
    float4 o1b = make_float4(a[2].y + b[4].y, a[2].w + b[5].y,
                             a[3].y + b[6].y, a[3].w + b[7].y);

    // Output is read once by the verifier — stream it (evict-first).
    float4* o0 = (float4*)(out) + 2 * i;
    float4* o1 = (float4*)(out + NOUT) + 2 * i;
    __stcs(o0,     o0a);
    __stcs(o0 + 1, o0b);
    __stcs(o1,     o1a);
    __stcs(o1 + 1, o1b);

    // Restore zeros for the next kernel_launch call / graph replay.
    // Default policy: the next splat's atomics want these lines in L2.
    float4 z4 = make_float4(0.f, 0.f, 0.f, 0.f);
    float2 z2 = make_float2(0.f, 0.f);
    #pragma unroll
    for (int k = 0; k < 4; k++) A4[4 * i + k] = z4;
    #pragma unroll
    for (int k = 0; k < 8; k++) Bv[8 * i + k] = z2;
}

extern "C" void kernel_launch(void* const* d_in, const int* in_sizes, int n_in,
                              void* d_out, int out_size) {
    const float4* x    = (const float4*)d_in[0];
    const float4* flow = (const float4*)d_in[1];
    const float4* mask = (const float4*)d_in[2];
    float* out = (float*)d_out;

    splat_kernel<<<NVOX / 4 / 256, 256>>>(x, flow, mask);
    finalize_kernel<<<(NOUT / 8) / 256, 256>>>(out);
}